// round 15
// baseline (speedup 1.0000x reference)
#include <cuda_runtime.h>
#include <math.h>

// Problem-fixed shapes
#define H   4096
#define W   4096
#define W2  8192

#define SCONST       1e-12f
#define EPS_V_FLOOR  (1e-32f / 6.0f)
#define PI_D         (3.14159265358979323846f / 1.1f)
#define PI_2         1.57079632679489662f

#define TILE_I 64
#define TILE_J 64
#define SM_H   68                    // TILE_I + 4
#define SM_W   68                    // TILE_J + 4 (even -> float2 alignment holds)
#define NBX    (W / TILE_J)          // 64
#define NBY    (H / TILE_I)          // 64
#define NBLK   (NBX * NBY)           // 4096

__device__ double g_partials[NBLK];
__device__ unsigned int g_ticket;    // zero-init; reset by last block each call

// ---------------------------------------------------------------------------
// Math tail: derivatives -> penalty value. (Validated: rel_err == 0.0)
// ---------------------------------------------------------------------------
__device__ __forceinline__ float penalty_val(float ex, float ey,
                                             float exx, float exy, float eyy,
                                             float c) {
    const float exs = ex + SCONST;
    const float eys = ey + SCONST;
    const float x2 = exs * exs;
    const float y2 = eys * eys;
    const float ev2 = x2 + y2;
    const float rinv = rsqrtf(ev2);
    const float ev = fmaxf(ev2 * rinv, EPS_V_FLOOR);
    float num = fmaf(y2, exx, x2 * eyy);
    num = fmaf(-2.0f * (exs * eys), exy, num);
    const float rinv3 = (rinv * rinv) * rinv;
    const float kabs = fabsf(num) * rinv3;

    // |atan(ev/c)| = atan(ev/|c|), reflected so the poly arg is in [0,1].
    const float ac = fabsf(c);
    const float z = __fdividef(fminf(ev, ac), fmaxf(ev, ac));
    const float w = z * z;
    float p = fmaf(w, -0.0040540580f, 0.0218612288f);
    p = fmaf(w, p, -0.0559098861f);
    p = fmaf(w, p, 0.0964200441f);
    p = fmaf(w, p, -0.1390853351f);
    p = fmaf(w, p, 0.1994653599f);
    p = fmaf(w, p, -0.3332985605f);
    p = fmaf(w, p, 0.9999993329f);
    float t = z * p;
    t = (ev > ac) ? (PI_2 - t) : t;

    return fmaxf(fmaf(kabs, t, -PI_D), 0.0f);  // fmaxf(NaN,0)=0 == nansum drop
}

__device__ __forceinline__ float warp_reduce_f(float v) {
#pragma unroll
    for (int o = 16; o > 0; o >>= 1)
        v += __shfl_xor_sync(0xffffffffu, v, o);
    return v;
}

// ---------------------------------------------------------------------------
// Main kernel: 64x64 output tile from a 68x68 smem tile. Each thread computes
// a 2-column pair over 8 row-strided iterations using aligned float2 LDS:
// 11 LDS.64 per 2 outputs (5.5 loads/elem vs 13 scalar). Interior blocks take
// a branch-free straight-line loop. Final reduction fused via ticket.
// ---------------------------------------------------------------------------
__global__ __launch_bounds__(256, 4)
void curve_kernel(const float* __restrict__ eps, const float* __restrict__ gs,
                  float* __restrict__ out) {
    __shared__ float tile[SM_H * SM_W];
    __shared__ double wpart[8];
    __shared__ double smr[256];
    __shared__ bool islast;

    const int tid = threadIdx.x;
    const int tx  = tid & 31;            // column-pair index within tile
    const int ty  = tid >> 5;            // row-group base (0..7)
    const int bi0 = blockIdx.y * TILE_I;
    const int bj0 = blockIdx.x * TILE_J;

    const float d    = __ldg(gs);
    const float rd   = 1.0f / d;
    const float r2d  = 0.5f / d;
    const float r2d2 = r2d * r2d;

    // Cooperative halo fill: rows clamped (clamped rows only feed outputs the
    // boundary path overrides), columns >= W use the reference's mirror map.
#pragma unroll
    for (int k = 0; k < 19; k++) {
        int idx = tid + k * 256;
        if (idx < SM_H * SM_W) {
            int r  = idx / SM_W;
            int cl = idx - r * SM_W;
            int gi = bi0 - 2 + r;
            gi = gi < 0 ? 0 : (gi > H - 1 ? H - 1 : gi);
            int gj = bj0 - 2 + cl;
            gj = gj < 0 ? 0 : (gj < W ? gj : (W2 - 1 - gj));
            tile[idx] = __ldg(eps + (size_t)gi * W + gj);
        }
    }
    __syncthreads();

#define S(a, b)  tile[(a) * SM_W + (b)]
#define S2(a, b) (*(const float2*)&tile[(a) * SM_W + (b)])   // b must be even

    const int sjp = 2 + 2 * tx;          // local column of pair start (even)
    float acc = 0.0f;

    const bool interior_block =
        (blockIdx.y != 0) & (blockIdx.y != NBY - 1) & (blockIdx.x != 0);

    if (interior_block) {
        // Branch-free: every element central. Mirror halo covers j >= W.
#pragma unroll
        for (int rr = 0; rr < 8; rr++) {
            const int si = ty + rr * 8 + 2;

            const float2 m2 = S2(si - 2, sjp);       // row -2: c, c+1
            const float2 u0 = S2(si - 1, sjp - 2);   // row -1: c-2, c-1
            const float2 u1 = S2(si - 1, sjp);       //         c,   c+1
            const float2 u2 = S2(si - 1, sjp + 2);   //         c+2, c+3
            const float2 c0 = S2(si,     sjp - 2);
            const float2 c1 = S2(si,     sjp);
            const float2 c2 = S2(si,     sjp + 2);
            const float2 d0 = S2(si + 1, sjp - 2);
            const float2 d1 = S2(si + 1, sjp);
            const float2 d2 = S2(si + 1, sjp + 2);
            const float2 p2 = S2(si + 2, sjp);

            // Shared vertical diffs at c-1, c, c+1, c+2
            const float va = d0.y - u0.y;
            const float vb = d1.x - u1.x;
            const float vc = d1.y - u1.y;
            const float vd = d2.x - u2.x;

            // Column A (c)
            {
                const float c   = c1.x;
                const float ex  = vb * r2d;
                const float ey  = (c1.y - c0.y) * r2d;
                const float exx = (fmaf(-2.0f, c, p2.x) + m2.x) * r2d2;
                const float eyy = (fmaf(-2.0f, c, c2.x) + c0.x) * r2d2;
                const float exy = (vc - va) * r2d2;
                acc += penalty_val(ex, ey, exx, exy, eyy, c);
            }
            // Column B (c+1)
            {
                const float c   = c1.y;
                const float ex  = vc * r2d;
                const float ey  = (c2.x - c1.x) * r2d;
                const float exx = (fmaf(-2.0f, c, p2.y) + m2.y) * r2d2;
                const float eyy = (fmaf(-2.0f, c, c2.y) + c0.y) * r2d2;
                const float exy = (vd - vb) * r2d2;
                acc += penalty_val(ex, ey, exx, exy, eyy, c);
            }
        }
    } else {
        // Boundary blocks (190 of 4096): per-element checks, R12-exact ops.
#pragma unroll
        for (int rr = 0; rr < 8; rr++) {
            const int li = ty + rr * 8;
            const int i  = bi0 + li;
            const int si = li + 2;
#pragma unroll
            for (int q = 0; q < 2; q++) {
                const int j  = bj0 + 2 * tx + q;
                const int sj = sjp + q;
                const float c = S(si, sj);
                float ex, ey, exx, exy, eyy;

                if ((i >= 2) & (i <= H - 3) & (j >= 2)) {
                    ex  = (S(si + 1, sj) - S(si - 1, sj)) * r2d;
                    ey  = (S(si, sj + 1) - S(si, sj - 1)) * r2d;
                    exx = (fmaf(-2.0f, c, S(si + 2, sj)) + S(si - 2, sj)) * r2d2;
                    eyy = (fmaf(-2.0f, c, S(si, sj + 2)) + S(si, sj - 2)) * r2d2;
                    exy = ((S(si + 1, sj + 1) - S(si - 1, sj + 1)) -
                           (S(si + 1, sj - 1) - S(si - 1, sj - 1))) * r2d2;
                } else {
                    auto EXf = [&](int gi_, int a, int b) -> float {
                        if (gi_ == 0)     return (S(a + 1, b) - S(a, b)) * rd;
                        if (gi_ == H - 1) return (S(a, b) - S(a - 1, b)) * rd;
                        return (S(a + 1, b) - S(a - 1, b)) * r2d;
                    };
                    auto EYf = [&](int gj_, int a, int b) -> float {
                        if (gj_ == 0) return (S(a, b + 1) - S(a, b)) * rd;
                        return (S(a, b + 1) - S(a, b - 1)) * r2d;  // right edge unreachable
                    };
                    ex = EXf(i, si, sj);
                    ey = EYf(j, si, sj);
                    if (i == 0)
                        exx = (EXf(1, si + 1, sj) - EXf(0, si, sj)) * rd;
                    else if (i == H - 1)
                        exx = (EXf(H - 1, si, sj) - EXf(H - 2, si - 1, sj)) * rd;
                    else
                        exx = (EXf(i + 1, si + 1, sj) - EXf(i - 1, si - 1, sj)) * r2d;
                    if (j == 0) {
                        exy = (EXf(i, si, sj + 1) - EXf(i, si, sj)) * rd;
                        eyy = (EYf(1, si, sj + 1) - EYf(0, si, sj)) * rd;
                    } else {
                        exy = (EXf(i, si, sj + 1) - EXf(i, si, sj - 1)) * r2d;
                        eyy = (EYf(j + 1, si, sj + 1) - EYf(j - 1, si, sj - 1)) * r2d;
                    }
                }
                acc += penalty_val(ex, ey, exx, exy, eyy, c);
            }
        }
    }

#undef S
#undef S2

    // Block reduction
    const float ws = warp_reduce_f(acc);
    if ((tid & 31) == 0) wpart[tid >> 5] = (double)ws;
    __syncthreads();
    if (tid == 0) {
        double s = 0.0;
#pragma unroll
        for (int w = 0; w < 8; w++) s += wpart[w];
        g_partials[blockIdx.y * NBX + blockIdx.x] = s;
        __threadfence();
        unsigned old = atomicAdd(&g_ticket, 1u);
        islast = (old == NBLK - 1);
    }
    __syncthreads();

    // Last block: deterministic final reduction (4-way ILP then tree)
    if (islast) {
        __threadfence();
        double s0 = 0.0, s1 = 0.0, s2 = 0.0, s3 = 0.0;
#pragma unroll
        for (int k = 0; k < NBLK / 1024; k++) {   // 4 iters of 4
            const int base = k * 1024 + tid;
            s0 += g_partials[base];
            s1 += g_partials[base + 256];
            s2 += g_partials[base + 512];
            s3 += g_partials[base + 768];
        }
        smr[tid] = (s0 + s1) + (s2 + s3);
        __syncthreads();
        for (int off = 128; off > 0; off >>= 1) {
            if (tid < off) smr[tid] += smr[tid + off];
            __syncthreads();
        }
        if (tid == 0) {
            // x2: mirror-symmetric halves contribute identically; ALPHA = 1
            out[0] = (float)(smr[0] * 2.0 * (double)d * (double)d);
            g_ticket = 0;                // reset for graph replay
        }
    }
}

extern "C" void kernel_launch(void* const* d_in, const int* in_sizes, int n_in,
                              void* d_out, int out_size) {
    const float* eps = (const float*)d_in[0];
    const float* gs  = (const float*)d_in[1];
    float* out = (float*)d_out;

    dim3 grid(NBX, NBY);     // 64 x 64 = 4096 blocks
    dim3 block(256);
    curve_kernel<<<grid, block>>>(eps, gs, out);
}

// round 16
// speedup vs baseline: 1.3380x; 1.3380x over previous
#include <cuda_runtime.h>
#include <math.h>

// Problem-fixed shapes
#define H   4096
#define W   4096
#define W2  8192

#define SCONST       1e-12f
#define EPS_V_FLOOR  (1e-32f / 6.0f)
#define PI_D         (3.14159265358979323846f / 1.1f)
#define PI_2         1.57079632679489662f

#define TILE_I 64
#define TILE_J 32
#define SM_H   68                    // TILE_I + 4
#define SM_W   36                    // TILE_J + 4
#define NBX    (W / TILE_J)          // 128
#define NBY    (H / TILE_I)          // 64
#define NBLK   (NBX * NBY)           // 8192

__device__ double g_partials[NBLK];
__device__ unsigned int g_ticket;    // zero-init; reset by last block each call

// ---------------------------------------------------------------------------
// Math tail (absolute-units form) for the boundary path. Validated rel_err 0.
// ---------------------------------------------------------------------------
__device__ __forceinline__ float penalty_val(float ex, float ey,
                                             float exx, float exy, float eyy,
                                             float c) {
    const float exs = ex + SCONST;
    const float eys = ey + SCONST;
    const float x2 = exs * exs;
    const float y2 = eys * eys;
    const float ev2 = x2 + y2;
    const float rinv = rsqrtf(ev2);
    const float ev = fmaxf(ev2 * rinv, EPS_V_FLOOR);
    float num = fmaf(y2, exx, x2 * eyy);
    num = fmaf(-2.0f * (exs * eys), exy, num);
    const float rinv3 = (rinv * rinv) * rinv;
    const float kabs = fabsf(num) * rinv3;

    const float ac = fabsf(c);
    const float z = __fdividef(fminf(ev, ac), fmaxf(ev, ac));
    const float w = z * z;
    float p = fmaf(w, -0.0040540580f, 0.0218612288f);
    p = fmaf(w, p, -0.0559098861f);
    p = fmaf(w, p, 0.0964200441f);
    p = fmaf(w, p, -0.1390853351f);
    p = fmaf(w, p, 0.1994653599f);
    p = fmaf(w, p, -0.3332985605f);
    p = fmaf(w, p, 0.9999993329f);
    float t = z * p;
    t = (ev > ac) ? (PI_2 - t) : t;

    return fmaxf(fmaf(kabs, t, -PI_D), 0.0f);  // fmaxf(NaN,0)=0 == nansum drop
}

__device__ __forceinline__ float warp_reduce_f(float v) {
#pragma unroll
    for (int o = 16; o > 0; o >>= 1)
        v += __shfl_xor_sync(0xffffffffu, v, o);
    return v;
}

// ---------------------------------------------------------------------------
// Main kernel: R12 skeleton (64x32 strip, 68x36 smem tile, 8 strided rows per
// thread, 13 consume-immediately LDS per output). Interior blocks (7882/8192)
// run a branch-free loop on RAW differences with the 1/(2d) factors folded
// into the tail. Boundary blocks keep the R12-exact composed operators.
// ---------------------------------------------------------------------------
__global__ __launch_bounds__(256, 5)
void curve_kernel(const float* __restrict__ eps, const float* __restrict__ gs,
                  float* __restrict__ out) {
    __shared__ float tile[SM_H * SM_W];
    __shared__ double wpart[8];
    __shared__ double smr[256];
    __shared__ bool islast;

    const int tid = threadIdx.x;
    const int tx  = tid & 31;            // column within tile
    const int ty  = tid >> 5;            // row-group base (0..7)
    const int bi0 = blockIdx.y * TILE_I;
    const int bj0 = blockIdx.x * TILE_J;

    const float d    = __ldg(gs);
    const float rd   = 1.0f / d;
    const float r2d  = 0.5f / d;
    const float r2d2 = r2d * r2d;
    const float sc2  = SCONST * (2.0f * d);   // SCONST in raw-difference units

    // Division-free cooperative halo fill. Rows clamped (clamped rows feed
    // only outputs the boundary path overrides); columns >= W mirror-mapped.
#pragma unroll
    for (int r = ty; r < SM_H; r += 8) {
        int gi = bi0 - 2 + r;
        gi = gi < 0 ? 0 : (gi > H - 1 ? H - 1 : gi);
        const float* rowp = eps + (size_t)gi * W;
#pragma unroll
        for (int cl = tx; cl < SM_W; cl += 32) {
            int gj = bj0 - 2 + cl;
            gj = gj < 0 ? 0 : (gj < W ? gj : (W2 - 1 - gj));
            tile[r * SM_W + cl] = __ldg(rowp + gj);
        }
    }
    __syncthreads();

#define S(a, b) tile[(a) * SM_W + (b)]

    const int j  = bj0 + tx;
    const int sj = tx + 2;
    float acc = 0.0f;

    const bool interior_block =
        (blockIdx.y != 0) & (blockIdx.y != NBY - 1) & (blockIdx.x != 0);

    if (interior_block) {
        // Branch-free: all elements central. Mirror halo covers j >= W, so no
        // right-edge case exists. Raw differences; scale folded into tail.
#pragma unroll
        for (int rr = 0; rr < 8; rr++) {
            const int si = ty + rr * 8 + 2;

            const float c = S(si, sj);
            const float ax  = S(si + 1, sj) - S(si - 1, sj);
            const float ay  = S(si, sj + 1) - S(si, sj - 1);
            const float axx = fmaf(-2.0f, c, S(si + 2, sj)) + S(si - 2, sj);
            const float ayy = fmaf(-2.0f, c, S(si, sj + 2)) + S(si, sj - 2);
            const float axy = (S(si + 1, sj + 1) - S(si - 1, sj + 1)) -
                              (S(si + 1, sj - 1) - S(si - 1, sj - 1));

            // Tail in raw units: ex = ax*r2d, exx = axx*r2d^2, etc.
            // k = r2d * rawnum / rav^3 ; ev = rav * r2d.
            const float axs = ax + sc2;
            const float ays = ay + sc2;
            const float x2 = axs * axs;
            const float y2 = ays * ays;
            const float rv2 = x2 + y2;
            const float rinv = rsqrtf(rv2);
            const float ev = fmaxf((rv2 * rinv) * r2d, EPS_V_FLOOR);
            float num = fmaf(y2, axx, x2 * ayy);
            num = fmaf(-2.0f * (axs * ays), axy, num);
            const float rinv3s = (rinv * rinv) * (rinv * r2d);
            const float kabs = fabsf(num) * rinv3s;

            const float ac = fabsf(c);
            const float z = __fdividef(fminf(ev, ac), fmaxf(ev, ac));
            const float w = z * z;
            float p = fmaf(w, -0.0040540580f, 0.0218612288f);
            p = fmaf(w, p, -0.0559098861f);
            p = fmaf(w, p, 0.0964200441f);
            p = fmaf(w, p, -0.1390853351f);
            p = fmaf(w, p, 0.1994653599f);
            p = fmaf(w, p, -0.3332985605f);
            p = fmaf(w, p, 0.9999993329f);
            float t = z * p;
            t = (ev > ac) ? (PI_2 - t) : t;

            acc += fmaxf(fmaf(kabs, t, -PI_D), 0.0f);
        }
    } else {
        // Boundary blocks (318 of 8192): R12-exact per-element path.
#pragma unroll
        for (int rr = 0; rr < 8; rr++) {
            const int li = ty + rr * 8;
            const int i  = bi0 + li;
            const int si = li + 2;

            const float c = S(si, sj);
            float ex, ey, exx, exy, eyy;

            if ((i >= 2) & (i <= H - 3) & (j >= 2)) {
                ex  = (S(si + 1, sj) - S(si - 1, sj)) * r2d;
                ey  = (S(si, sj + 1) - S(si, sj - 1)) * r2d;
                exx = (fmaf(-2.0f, c, S(si + 2, sj)) + S(si - 2, sj)) * r2d2;
                eyy = (fmaf(-2.0f, c, S(si, sj + 2)) + S(si, sj - 2)) * r2d2;
                exy = ((S(si + 1, sj + 1) - S(si - 1, sj + 1)) -
                       (S(si + 1, sj - 1) - S(si - 1, sj - 1))) * r2d2;
            } else {
                auto EXf = [&](int gi_, int a, int b) -> float {
                    if (gi_ == 0)     return (S(a + 1, b) - S(a, b)) * rd;
                    if (gi_ == H - 1) return (S(a, b) - S(a - 1, b)) * rd;
                    return (S(a + 1, b) - S(a - 1, b)) * r2d;
                };
                auto EYf = [&](int gj_, int a, int b) -> float {
                    if (gj_ == 0) return (S(a, b + 1) - S(a, b)) * rd;
                    return (S(a, b + 1) - S(a, b - 1)) * r2d;  // right edge unreachable
                };
                ex = EXf(i, si, sj);
                ey = EYf(j, si, sj);
                if (i == 0)
                    exx = (EXf(1, si + 1, sj) - EXf(0, si, sj)) * rd;
                else if (i == H - 1)
                    exx = (EXf(H - 1, si, sj) - EXf(H - 2, si - 1, sj)) * rd;
                else
                    exx = (EXf(i + 1, si + 1, sj) - EXf(i - 1, si - 1, sj)) * r2d;
                if (j == 0) {
                    exy = (EXf(i, si, sj + 1) - EXf(i, si, sj)) * rd;
                    eyy = (EYf(1, si, sj + 1) - EYf(0, si, sj)) * rd;
                } else {
                    exy = (EXf(i, si, sj + 1) - EXf(i, si, sj - 1)) * r2d;
                    eyy = (EYf(j + 1, si, sj + 1) - EYf(j - 1, si, sj - 1)) * r2d;
                }
            }

            acc += penalty_val(ex, ey, exx, exy, eyy, c);
        }
    }

#undef S

    // Block reduction
    const float ws = warp_reduce_f(acc);
    if ((tid & 31) == 0) wpart[tid >> 5] = (double)ws;
    __syncthreads();
    if (tid == 0) {
        double s = 0.0;
#pragma unroll
        for (int w = 0; w < 8; w++) s += wpart[w];
        g_partials[blockIdx.y * NBX + blockIdx.x] = s;
        __threadfence();
        unsigned old = atomicAdd(&g_ticket, 1u);
        islast = (old == NBLK - 1);
    }
    __syncthreads();

    // Last block: deterministic final reduction (4-way ILP then tree)
    if (islast) {
        __threadfence();
        double s0 = 0.0, s1 = 0.0, s2 = 0.0, s3 = 0.0;
#pragma unroll
        for (int k = 0; k < NBLK / 1024; k++) {   // 8 iters of 4
            const int base = k * 1024 + tid;
            s0 += g_partials[base];
            s1 += g_partials[base + 256];
            s2 += g_partials[base + 512];
            s3 += g_partials[base + 768];
        }
        smr[tid] = (s0 + s1) + (s2 + s3);
        __syncthreads();
        for (int off = 128; off > 0; off >>= 1) {
            if (tid < off) smr[tid] += smr[tid + off];
            __syncthreads();
        }
        if (tid == 0) {
            // x2: mirror-symmetric halves contribute identically; ALPHA = 1
            out[0] = (float)(smr[0] * 2.0 * (double)d * (double)d);
            g_ticket = 0;                // reset for graph replay
        }
    }
}

extern "C" void kernel_launch(void* const* d_in, const int* in_sizes, int n_in,
                              void* d_out, int out_size) {
    const float* eps = (const float*)d_in[0];
    const float* gs  = (const float*)d_in[1];
    float* out = (float*)d_out;

    dim3 grid(NBX, NBY);     // 128 x 64 = 8192 blocks
    dim3 block(256);
    curve_kernel<<<grid, block>>>(eps, gs, out);
}

// round 17
// speedup vs baseline: 1.3765x; 1.0288x over previous
#include <cuda_runtime.h>
#include <math.h>

// Problem-fixed shapes
#define H   4096
#define W   4096
#define W2  8192

#define SCONST       1e-12f
#define EPS_V_FLOOR  (1e-32f / 6.0f)
#define PI_D         (3.14159265358979323846f / 1.1f)
#define PI_2         1.57079632679489662f

#define TILE_I 64
#define TILE_J 32
#define SM_H   68                    // TILE_I + 4
#define SM_W   36                    // TILE_J + 4
#define NBX    (W / TILE_J)          // 128
#define NBY    (H / TILE_I)          // 64
#define NBLK   (NBX * NBY)           // 8192

__device__ double g_partials[NBLK];
__device__ unsigned int g_ticket;    // zero-init; reset by last block each call

// ---------------------------------------------------------------------------
// Math tail (absolute units) for the boundary path. Validated rel_err == 0.
// ---------------------------------------------------------------------------
__device__ __forceinline__ float penalty_val(float ex, float ey,
                                             float exx, float exy, float eyy,
                                             float c) {
    const float exs = ex + SCONST;
    const float eys = ey + SCONST;
    const float x2 = exs * exs;
    const float y2 = eys * eys;
    const float ev2 = x2 + y2;
    const float rinv = rsqrtf(ev2);
    const float ev = fmaxf(ev2 * rinv, EPS_V_FLOOR);
    float num = fmaf(y2, exx, x2 * eyy);
    num = fmaf(-2.0f * (exs * eys), exy, num);
    const float rinv3 = (rinv * rinv) * rinv;
    const float kabs = fabsf(num) * rinv3;

    const float ac = fabsf(c);
    const float z = __fdividef(fminf(ev, ac), fmaxf(ev, ac));
    const float w = z * z;
    float p = fmaf(w, -0.0040540580f, 0.0218612288f);
    p = fmaf(w, p, -0.0559098861f);
    p = fmaf(w, p, 0.0964200441f);
    p = fmaf(w, p, -0.1390853351f);
    p = fmaf(w, p, 0.1994653599f);
    p = fmaf(w, p, -0.3332985605f);
    p = fmaf(w, p, 0.9999993329f);
    float t = z * p;
    t = (ev > ac) ? (PI_2 - t) : t;

    return fmaxf(fmaf(kabs, t, -PI_D), 0.0f);  // fmaxf(NaN,0)=0 == nansum drop
}

__device__ __forceinline__ float warp_reduce_f(float v) {
#pragma unroll
    for (int o = 16; o > 0; o >>= 1)
        v += __shfl_xor_sync(0xffffffffu, v, o);
    return v;
}

// ---------------------------------------------------------------------------
// Main kernel: 64x32 strip, 68x36 smem tile. Interior blocks: each thread
// walks 8 CONSECUTIVE rows of one column with rolling register windows
// (center 5-tall, j-1 / j+1 3-tall) -> only 5 LDS per element (vs 13),
// 8 floats persistent across the math tail (no spill). Boundary blocks
// (318/8192) keep the validated composed-operator path. Ticket reduction.
// ---------------------------------------------------------------------------
__global__ __launch_bounds__(256, 4)
void curve_kernel(const float* __restrict__ eps, const float* __restrict__ gs,
                  float* __restrict__ out) {
    __shared__ float tile[SM_H * SM_W];
    __shared__ double wpart[8];
    __shared__ double smr[256];
    __shared__ bool islast;

    const int tid = threadIdx.x;
    const int tx  = tid & 31;            // column within tile
    const int ty  = tid >> 5;            // 8-consecutive-row group (0..7)
    const int bi0 = blockIdx.y * TILE_I;
    const int bj0 = blockIdx.x * TILE_J;

    const float d    = __ldg(gs);
    const float rd   = 1.0f / d;
    const float r2d  = 0.5f / d;
    const float r2d2 = r2d * r2d;
    const float sc2  = SCONST * (2.0f * d);   // SCONST in raw-difference units

    // Division-free cooperative halo fill. Rows clamped (clamped rows feed
    // only outputs the boundary path overrides); columns >= W mirror-mapped.
#pragma unroll
    for (int r = ty; r < SM_H; r += 8) {
        int gi = bi0 - 2 + r;
        gi = gi < 0 ? 0 : (gi > H - 1 ? H - 1 : gi);
        const float* rowp = eps + (size_t)gi * W;
#pragma unroll
        for (int cl = tx; cl < SM_W; cl += 32) {
            int gj = bj0 - 2 + cl;
            gj = gj < 0 ? 0 : (gj < W ? gj : (W2 - 1 - gj));
            tile[r * SM_W + cl] = __ldg(rowp + gj);
        }
    }
    __syncthreads();

#define S(a, b) tile[(a) * SM_W + (b)]

    const int j  = bj0 + tx;
    const int sj = tx + 2;
    float acc = 0.0f;

    const bool interior_block =
        (blockIdx.y != 0) & (blockIdx.y != NBY - 1) & (blockIdx.x != 0);

    if (interior_block) {
        const int si0 = ty * 8 + 2;      // smem row of this thread's first output

        // Rolling windows: center column 5-tall (a0..a4), j-1 (l1..l3),
        // j+1 (q1..q3). Preload tops.
        float a0 = S(si0 - 2, sj);
        float a1 = S(si0 - 1, sj);
        float a2 = S(si0,     sj);
        float a3 = S(si0 + 1, sj);
        float l1 = S(si0 - 1, sj - 1);
        float l2 = S(si0,     sj - 1);
        float q1 = S(si0 - 1, sj + 1);
        float q2 = S(si0,     sj + 1);

#pragma unroll
        for (int rr = 0; rr < 8; rr++) {
            const int si = si0 + rr;
            const float a4 = S(si + 2, sj);      // new center bottom
            const float l3 = S(si + 1, sj - 1);  // new left bottom
            const float q3 = S(si + 1, sj + 1);  // new right bottom
            const float ll = S(si, sj - 2);
            const float qq = S(si, sj + 2);

            const float c   = a2;
            const float ax  = a3 - a1;
            const float ay  = q2 - l2;
            const float axx = fmaf(-2.0f, c, a4) + a0;
            const float ayy = fmaf(-2.0f, c, qq) + ll;
            const float axy = (q3 - q1) - (l3 - l1);

            // Raw-units tail (validated): ex = ax*r2d etc., scale folded in.
            const float axs = ax + sc2;
            const float ays = ay + sc2;
            const float x2 = axs * axs;
            const float y2 = ays * ays;
            const float rv2 = x2 + y2;
            const float rinv = rsqrtf(rv2);
            const float ev = fmaxf((rv2 * rinv) * r2d, EPS_V_FLOOR);
            float num = fmaf(y2, axx, x2 * ayy);
            num = fmaf(-2.0f * (axs * ays), axy, num);
            const float rinv3s = (rinv * rinv) * (rinv * r2d);
            const float kabs = fabsf(num) * rinv3s;

            const float ac = fabsf(c);
            const float z = __fdividef(fminf(ev, ac), fmaxf(ev, ac));
            const float w = z * z;
            float p = fmaf(w, -0.0040540580f, 0.0218612288f);
            p = fmaf(w, p, -0.0559098861f);
            p = fmaf(w, p, 0.0964200441f);
            p = fmaf(w, p, -0.1390853351f);
            p = fmaf(w, p, 0.1994653599f);
            p = fmaf(w, p, -0.3332985605f);
            p = fmaf(w, p, 0.9999993329f);
            float t = z * p;
            t = (ev > ac) ? (PI_2 - t) : t;

            acc += fmaxf(fmaf(kabs, t, -PI_D), 0.0f);

            // Roll windows (renamed by unroll; no MOVs)
            a0 = a1; a1 = a2; a2 = a3; a3 = a4;
            l1 = l2; l2 = l3;
            q1 = q2; q2 = q3;
        }
    } else {
        // Boundary blocks: validated per-element composed-operator path.
#pragma unroll
        for (int rr = 0; rr < 8; rr++) {
            const int li = ty * 8 + rr;
            const int i  = bi0 + li;
            const int si = li + 2;

            const float c = S(si, sj);
            float ex, ey, exx, exy, eyy;

            if ((i >= 2) & (i <= H - 3) & (j >= 2)) {
                ex  = (S(si + 1, sj) - S(si - 1, sj)) * r2d;
                ey  = (S(si, sj + 1) - S(si, sj - 1)) * r2d;
                exx = (fmaf(-2.0f, c, S(si + 2, sj)) + S(si - 2, sj)) * r2d2;
                eyy = (fmaf(-2.0f, c, S(si, sj + 2)) + S(si, sj - 2)) * r2d2;
                exy = ((S(si + 1, sj + 1) - S(si - 1, sj + 1)) -
                       (S(si + 1, sj - 1) - S(si - 1, sj - 1))) * r2d2;
            } else {
                auto EXf = [&](int gi_, int a, int b) -> float {
                    if (gi_ == 0)     return (S(a + 1, b) - S(a, b)) * rd;
                    if (gi_ == H - 1) return (S(a, b) - S(a - 1, b)) * rd;
                    return (S(a + 1, b) - S(a - 1, b)) * r2d;
                };
                auto EYf = [&](int gj_, int a, int b) -> float {
                    if (gj_ == 0) return (S(a, b + 1) - S(a, b)) * rd;
                    return (S(a, b + 1) - S(a, b - 1)) * r2d;  // right edge unreachable
                };
                ex = EXf(i, si, sj);
                ey = EYf(j, si, sj);
                if (i == 0)
                    exx = (EXf(1, si + 1, sj) - EXf(0, si, sj)) * rd;
                else if (i == H - 1)
                    exx = (EXf(H - 1, si, sj) - EXf(H - 2, si - 1, sj)) * rd;
                else
                    exx = (EXf(i + 1, si + 1, sj) - EXf(i - 1, si - 1, sj)) * r2d;
                if (j == 0) {
                    exy = (EXf(i, si, sj + 1) - EXf(i, si, sj)) * rd;
                    eyy = (EYf(1, si, sj + 1) - EYf(0, si, sj)) * rd;
                } else {
                    exy = (EXf(i, si, sj + 1) - EXf(i, si, sj - 1)) * r2d;
                    eyy = (EYf(j + 1, si, sj + 1) - EYf(j - 1, si, sj - 1)) * r2d;
                }
            }

            acc += penalty_val(ex, ey, exx, exy, eyy, c);
        }
    }

#undef S

    // Block reduction
    const float ws = warp_reduce_f(acc);
    if ((tid & 31) == 0) wpart[tid >> 5] = (double)ws;
    __syncthreads();
    if (tid == 0) {
        double s = 0.0;
#pragma unroll
        for (int w = 0; w < 8; w++) s += wpart[w];
        g_partials[blockIdx.y * NBX + blockIdx.x] = s;
        __threadfence();
        unsigned old = atomicAdd(&g_ticket, 1u);
        islast = (old == NBLK - 1);
    }
    __syncthreads();

    // Last block: deterministic final reduction (4-way ILP then tree)
    if (islast) {
        __threadfence();
        double s0 = 0.0, s1 = 0.0, s2 = 0.0, s3 = 0.0;
#pragma unroll
        for (int k = 0; k < NBLK / 1024; k++) {   // 8 iters of 4
            const int base = k * 1024 + tid;
            s0 += g_partials[base];
            s1 += g_partials[base + 256];
            s2 += g_partials[base + 512];
            s3 += g_partials[base + 768];
        }
        smr[tid] = (s0 + s1) + (s2 + s3);
        __syncthreads();
        for (int off = 128; off > 0; off >>= 1) {
            if (tid < off) smr[tid] += smr[tid + off];
            __syncthreads();
        }
        if (tid == 0) {
            // x2: mirror-symmetric halves contribute identically; ALPHA = 1
            out[0] = (float)(smr[0] * 2.0 * (double)d * (double)d);
            g_ticket = 0;                // reset for graph replay
        }
    }
}

extern "C" void kernel_launch(void* const* d_in, const int* in_sizes, int n_in,
                              void* d_out, int out_size) {
    const float* eps = (const float*)d_in[0];
    const float* gs  = (const float*)d_in[1];
    float* out = (float*)d_out;

    dim3 grid(NBX, NBY);     // 128 x 64 = 8192 blocks
    dim3 block(256);
    curve_kernel<<<grid, block>>>(eps, gs, out);
}